// round 3
// baseline (speedup 1.0000x reference)
#include <cuda_runtime.h>
#include <cstdint>

// RGCNHighMem: out[dst] += feat[src] @ W[etype]
// v3: single-pass scatter into padded per-relation buckets, then
// thread-per-edge main kernel: W in smem (broadcast LDS), feat row in regs,
// 16 packed f32x2 accumulators, red.add.v4 scatter. No intra-loop syncs.

#define RELS   64
#define EPB    256          // edges per main-kernel block
#define SCHUNK 512          // edges per scatter block
#define CAP    8192         // per-relation bucket capacity (max expected ~3.4K)
#define MAXK   (CAP / EPB)  // 32 chunks per relation max

__device__ int g_cnt[RELS];
__device__ unsigned long long g_edges[RELS * CAP];  // packed (src | dst<<32)

// Single-pass scatter: block-local histogram -> one global reservation per
// relation -> rank-and-store packed edges into relation buckets.
__global__ __launch_bounds__(256)
void k_scatter(const int* __restrict__ src, const int* __restrict__ dst,
               const int* __restrict__ et, int E) {
    __shared__ int cnt[RELS], base[RELS];
    int tid = threadIdx.x;
    int b0 = blockIdx.x * SCHUNK;
    int b1 = min(E, b0 + SCHUNK);
    if (tid < RELS) cnt[tid] = 0;
    __syncthreads();

    int t0 = -1, t1 = -1;
    int e0 = b0 + tid, e1 = b0 + tid + 256;
    if (e0 < b1) { t0 = et[e0]; atomicAdd(&cnt[t0], 1); }
    if (e1 < b1) { t1 = et[e1]; atomicAdd(&cnt[t1], 1); }
    __syncthreads();

    if (tid < RELS) {
        int v = cnt[tid];
        base[tid] = v ? atomicAdd(&g_cnt[tid], v) : 0;
        cnt[tid] = 0;
    }
    __syncthreads();

    if (t0 >= 0) {
        int p = base[t0] + atomicAdd(&cnt[t0], 1);
        g_edges[t0 * CAP + p] =
            (unsigned long long)(unsigned)src[e0] |
            ((unsigned long long)(unsigned)dst[e0] << 32);
    }
    if (t1 >= 0) {
        int p = base[t1] + atomicAdd(&cnt[t1], 1);
        g_edges[t1 * CAP + p] =
            (unsigned long long)(unsigned)src[e1] |
            ((unsigned long long)(unsigned)dst[e1] << 32);
    }
}

// Main: block = (relation, chunk) from blockIdx; 128 threads, thread-per-edge.
// W[r] (4KB) lives in smem, read via broadcast LDS.128. Each thread:
//  - loads its edge's 128B feat row into 8 float4 regs
//  - dup-packs each feat scalar to f32x2 (1 ALU mov), FMAs against W col-pairs
//  - 16 f32x2 accumulators = 32 output columns
//  - 8x red.global.add.v4.f32 into out[dst]
__global__ __launch_bounds__(128, 5)
void k_main(const float4* __restrict__ feat4, const float4* __restrict__ W4,
            float* __restrict__ out) {
    int r = blockIdx.x >> 5;            // MAXK = 32
    int k = blockIdx.x & (MAXK - 1);
    int cnt = g_cnt[r];
    int segs = k * EPB;
    if (segs >= cnt) return;            // block-uniform: safe before barrier
    int sege = min(cnt, segs + EPB);
    const unsigned long long* eb = g_edges + (size_t)r * CAP;

    // Cooperative copy of W[r] (1024 floats = 256 float4) into smem.
    __shared__ float4 Wsh[256];
    int tid = threadIdx.x;
    Wsh[tid]       = W4[r * 256 + tid];
    Wsh[tid + 128] = W4[r * 256 + tid + 128];
    __syncthreads();
    const ulonglong2* Ws2 = (const ulonglong2*)Wsh;   // [32 rows][8 quads]

    int e = segs + tid;
    unsigned long long pk = (e < sege) ? eb[e] : 0ULL;

    for (; e < sege; e += 128) {
        // prefetch next edge record
        unsigned long long pk_next = (e + 128 < sege) ? eb[e + 128] : 0ULL;
        int s = (int)(unsigned)pk;
        int d = (int)(pk >> 32);

        // load feat row (128B = one L2 line)
        float4 ff[8];
        #pragma unroll
        for (int q = 0; q < 8; q++) ff[q] = feat4[s * 8 + q];

        unsigned long long acc[16];
        #pragma unroll
        for (int j = 0; j < 16; j++) acc[j] = 0ULL;

        #pragma unroll
        for (int i = 0; i < 32; i++) {
            float fs;
            {
                float4 v = ff[i >> 2];
                fs = (i & 2) ? ((i & 1) ? v.w : v.z)
                             : ((i & 1) ? v.y : v.x);
            }
            unsigned long long fd;
            asm("mov.b64 %0, {%1, %1};" : "=l"(fd) : "r"(__float_as_uint(fs)));
            #pragma unroll
            for (int q = 0; q < 8; q++) {
                ulonglong2 wv = Ws2[i * 8 + q];     // broadcast LDS.128
                asm("fma.rn.f32x2 %0, %1, %2, %0;"
                    : "+l"(acc[2 * q]) : "l"(fd), "l"(wv.x));
                asm("fma.rn.f32x2 %0, %1, %2, %0;"
                    : "+l"(acc[2 * q + 1]) : "l"(fd), "l"(wv.y));
            }
        }

        float* p = out + (size_t)d * 32;
        #pragma unroll
        for (int q = 0; q < 8; q++) {
            unsigned ax, ay, az, aw;
            asm("mov.b64 {%0,%1}, %2;" : "=r"(ax), "=r"(ay) : "l"(acc[2 * q]));
            asm("mov.b64 {%0,%1}, %2;" : "=r"(az), "=r"(aw) : "l"(acc[2 * q + 1]));
            asm volatile("red.global.add.v4.f32 [%0], {%1,%2,%3,%4};"
                         :: "l"(p + q * 4),
                            "f"(__uint_as_float(ax)), "f"(__uint_as_float(ay)),
                            "f"(__uint_as_float(az)), "f"(__uint_as_float(aw))
                         : "memory");
        }
        pk = pk_next;
    }
}

extern "C" void kernel_launch(void* const* d_in, const int* in_sizes, int n_in,
                              void* d_out, int out_size) {
    const float* feat = (const float*)d_in[0];
    const float* W    = (const float*)d_in[1];
    const int*   src  = (const int*)d_in[2];
    const int*   dst  = (const int*)d_in[3];
    const int*   et   = (const int*)d_in[4];
    int E = in_sizes[2];

    void* cnt_addr = nullptr;
    cudaGetSymbolAddress(&cnt_addr, g_cnt);

    cudaMemsetAsync(d_out, 0, (size_t)out_size * sizeof(float), 0);
    cudaMemsetAsync(cnt_addr, 0, RELS * sizeof(int), 0);
    k_scatter<<<(E + SCHUNK - 1) / SCHUNK, 256>>>(src, dst, et, E);
    k_main<<<RELS * MAXK, 128>>>((const float4*)feat, (const float4*)W,
                                 (float*)d_out);
}

// round 4
// speedup vs baseline: 1.0306x; 1.0306x over previous
#include <cuda_runtime.h>
#include <cstdint>

// RGCNHighMem: out[dst] += feat[src] @ W[etype]
// v4: single-pass scatter into padded per-relation buckets, then main kernel
// with 2 edges per thread: W in smem (broadcast LDS.128 shared by both edges),
// feat rows in regs, column halves to bound register pressure.

#define RELS   64
#define EPB    512          // edges per main-kernel block (128 thr x 2 edges x 2 iters)
#define SCHUNK 512          // edges per scatter block
#define CAP    8192         // per-relation bucket capacity (max expected ~3.4K)
#define MAXK   (CAP / EPB)  // 16 chunks per relation max

__device__ int g_cnt[RELS];
__device__ unsigned long long g_edges[RELS * CAP];  // packed (src | dst<<32)

// Single-pass scatter: block-local histogram -> one global reservation per
// relation -> rank-and-store packed edges into relation buckets.
__global__ __launch_bounds__(256)
void k_scatter(const int* __restrict__ src, const int* __restrict__ dst,
               const int* __restrict__ et, int E) {
    __shared__ int cnt[RELS], base[RELS];
    int tid = threadIdx.x;
    int b0 = blockIdx.x * SCHUNK;
    int b1 = min(E, b0 + SCHUNK);
    if (tid < RELS) cnt[tid] = 0;
    __syncthreads();

    int t0 = -1, t1 = -1;
    int e0 = b0 + tid, e1 = b0 + tid + 256;
    if (e0 < b1) { t0 = et[e0]; atomicAdd(&cnt[t0], 1); }
    if (e1 < b1) { t1 = et[e1]; atomicAdd(&cnt[t1], 1); }
    __syncthreads();

    if (tid < RELS) {
        int v = cnt[tid];
        base[tid] = v ? atomicAdd(&g_cnt[tid], v) : 0;
        cnt[tid] = 0;
    }
    __syncthreads();

    if (t0 >= 0) {
        int p = base[t0] + atomicAdd(&cnt[t0], 1);
        g_edges[t0 * CAP + p] =
            (unsigned long long)(unsigned)src[e0] |
            ((unsigned long long)(unsigned)dst[e0] << 32);
    }
    if (t1 >= 0) {
        int p = base[t1] + atomicAdd(&cnt[t1], 1);
        g_edges[t1 * CAP + p] =
            (unsigned long long)(unsigned)src[e1] |
            ((unsigned long long)(unsigned)dst[e1] << 32);
    }
}

// Main: block = (relation, chunk); 128 threads; 2 edges per thread per iter.
// W[r] (4KB) in smem via broadcast LDS.128; each LDS feeds 4 FFMA2.
// Columns processed in two halves of 16 to keep acc regs at 32.
__global__ __launch_bounds__(128, 4)
void k_main(const float4* __restrict__ feat4, const float4* __restrict__ W4,
            float* __restrict__ out) {
    int r = blockIdx.x >> 4;            // MAXK = 16
    int k = blockIdx.x & (MAXK - 1);
    int cnt = g_cnt[r];
    int segs = k * EPB;
    if (segs >= cnt) return;            // block-uniform: safe before barrier
    int sege = min(cnt, segs + EPB);
    const unsigned long long* eb = g_edges + (size_t)r * CAP;

    // Cooperative copy of W[r] (1024 floats = 256 float4) into smem.
    __shared__ float4 Wsh[256];
    int tid = threadIdx.x;
    Wsh[tid]       = W4[r * 256 + tid];
    Wsh[tid + 128] = W4[r * 256 + tid + 128];
    __syncthreads();
    const ulonglong2* Ws2 = (const ulonglong2*)Wsh;   // [32 rows][8 quads]

    for (int e0 = segs + tid * 2; e0 < sege; e0 += 256) {
        int eA = e0;
        int eB = e0 + 1;
        bool vB = eB < sege;
        unsigned long long pkA = eb[eA];
        unsigned long long pkB = eb[vB ? eB : eA];
        int sA = (int)(unsigned)pkA, dA = (int)(pkA >> 32);
        int sB = (int)(unsigned)pkB, dB = (int)(pkB >> 32);

        // Load both feat rows (128B each), register-resident across halves.
        float4 fA[8], fB[8];
        #pragma unroll
        for (int q = 0; q < 8; q++) fA[q] = feat4[sA * 8 + q];
        #pragma unroll
        for (int q = 0; q < 8; q++) fB[q] = feat4[sB * 8 + q];

        float* pA = out + (size_t)dA * 32;
        float* pB = out + (size_t)dB * 32;

        #pragma unroll
        for (int h = 0; h < 2; h++) {
            unsigned long long aA[8], aB[8];
            #pragma unroll
            for (int j = 0; j < 8; j++) { aA[j] = 0ULL; aB[j] = 0ULL; }

            #pragma unroll
            for (int i = 0; i < 32; i++) {
                float4 vA4 = fA[i >> 2], vB4 = fB[i >> 2];
                float fsA = (i & 2) ? ((i & 1) ? vA4.w : vA4.z)
                                    : ((i & 1) ? vA4.y : vA4.x);
                float fsB = (i & 2) ? ((i & 1) ? vB4.w : vB4.z)
                                    : ((i & 1) ? vB4.y : vB4.x);
                unsigned long long fdA, fdB;
                asm("mov.b64 %0, {%1, %1};" : "=l"(fdA)
                    : "r"(__float_as_uint(fsA)));
                asm("mov.b64 %0, {%1, %1};" : "=l"(fdB)
                    : "r"(__float_as_uint(fsB)));
                #pragma unroll
                for (int q = 0; q < 4; q++) {
                    ulonglong2 wv = Ws2[i * 8 + h * 4 + q];  // broadcast LDS.128
                    asm("fma.rn.f32x2 %0, %1, %2, %0;"
                        : "+l"(aA[2 * q]) : "l"(fdA), "l"(wv.x));
                    asm("fma.rn.f32x2 %0, %1, %2, %0;"
                        : "+l"(aA[2 * q + 1]) : "l"(fdA), "l"(wv.y));
                    asm("fma.rn.f32x2 %0, %1, %2, %0;"
                        : "+l"(aB[2 * q]) : "l"(fdB), "l"(wv.x));
                    asm("fma.rn.f32x2 %0, %1, %2, %0;"
                        : "+l"(aB[2 * q + 1]) : "l"(fdB), "l"(wv.y));
                }
            }

            #pragma unroll
            for (int q = 0; q < 4; q++) {
                unsigned ax, ay, az, aw;
                asm("mov.b64 {%0,%1}, %2;" : "=r"(ax), "=r"(ay)
                    : "l"(aA[2 * q]));
                asm("mov.b64 {%0,%1}, %2;" : "=r"(az), "=r"(aw)
                    : "l"(aA[2 * q + 1]));
                asm volatile("red.global.add.v4.f32 [%0], {%1,%2,%3,%4};"
                             :: "l"(pA + h * 16 + q * 4),
                                "f"(__uint_as_float(ax)), "f"(__uint_as_float(ay)),
                                "f"(__uint_as_float(az)), "f"(__uint_as_float(aw))
                             : "memory");
            }
            if (vB) {
                #pragma unroll
                for (int q = 0; q < 4; q++) {
                    unsigned ax, ay, az, aw;
                    asm("mov.b64 {%0,%1}, %2;" : "=r"(ax), "=r"(ay)
                        : "l"(aB[2 * q]));
                    asm("mov.b64 {%0,%1}, %2;" : "=r"(az), "=r"(aw)
                        : "l"(aB[2 * q + 1]));
                    asm volatile("red.global.add.v4.f32 [%0], {%1,%2,%3,%4};"
                                 :: "l"(pB + h * 16 + q * 4),
                                    "f"(__uint_as_float(ax)), "f"(__uint_as_float(ay)),
                                    "f"(__uint_as_float(az)), "f"(__uint_as_float(aw))
                                 : "memory");
                }
            }
        }
    }
}

extern "C" void kernel_launch(void* const* d_in, const int* in_sizes, int n_in,
                              void* d_out, int out_size) {
    const float* feat = (const float*)d_in[0];
    const float* W    = (const float*)d_in[1];
    const int*   src  = (const int*)d_in[2];
    const int*   dst  = (const int*)d_in[3];
    const int*   et   = (const int*)d_in[4];
    int E = in_sizes[2];

    void* cnt_addr = nullptr;
    cudaGetSymbolAddress(&cnt_addr, g_cnt);

    cudaMemsetAsync(d_out, 0, (size_t)out_size * sizeof(float), 0);
    cudaMemsetAsync(cnt_addr, 0, RELS * sizeof(int), 0);
    k_scatter<<<(E + SCHUNK - 1) / SCHUNK, 256>>>(src, dst, et, E);
    k_main<<<RELS * MAXK, 128>>>((const float4*)feat, (const float4*)W,
                                 (float*)d_out);
}